// round 13
// baseline (speedup 1.0000x reference)
#include <cuda_runtime.h>
#include <cuda_fp16.h>
#include <cstdint>
#include <math.h>

// Fixed shapes: B=8, C=256, H=128, W=128, heads=8, e=32
#define MROWS 131072
#define CDIM  256
#define NELEM (MROWS * CDIM)

// Scratch (allocation-free rule: __device__ globals)
__device__ __align__(16) __half g_q[NELEM];
__device__ __align__(16) __half g_k[NELEM];
__device__ __align__(16) __half g_v[NELEM];
__device__ __align__(16) __half g_attn[NELEM];
// Preconverted fp16 weights, swizzled chunk-major:
// 6 mats x 8 ksteps x [256 rows][32 cols] fp16 (16KB blocks)
// mats: 0=Wscale 1=Wshift 2=Wq 3=Wk 4=Wv 5=Wout
__device__ __align__(16) uint16_t g_wh[6 * 8 * 8192];

// ---------------------------------------------------------------------------
// PTX helpers
// ---------------------------------------------------------------------------
__device__ __forceinline__ uint32_t smem_u32(const void* p) {
    uint32_t a;
    asm("{ .reg .u64 t; cvta.to.shared.u64 t, %1; cvt.u32.u64 %0, t; }"
        : "=r"(a) : "l"(p));
    return a;
}

#define LDSM_X4(r0, r1, r2, r3, addr)                                         \
    asm volatile("ldmatrix.sync.aligned.m8n8.x4.shared.b16 {%0,%1,%2,%3}, [%4];" \
                 : "=r"(r0), "=r"(r1), "=r"(r2), "=r"(r3) : "r"(addr))

#define MMA16816(d, a, b0, b1)                                                \
    asm volatile("mma.sync.aligned.m16n8k16.row.col.f32.f16.f16.f32 "         \
                 "{%0,%1,%2,%3}, {%4,%5,%6,%7}, {%8,%9}, {%0,%1,%2,%3};"      \
                 : "+f"((d)[0]), "+f"((d)[1]), "+f"((d)[2]), "+f"((d)[3])     \
                 : "r"((a)[0]), "r"((a)[1]), "r"((a)[2]), "r"((a)[3]),        \
                   "r"(b0), "r"(b1))

#define CP_ASYNC16(dst, src)                                                  \
    asm volatile("cp.async.cg.shared.global [%0], [%1], 16;" ::               \
                 "r"(dst), "l"(src) : "memory")
#define CP_COMMIT()  asm volatile("cp.async.commit_group;" ::: "memory")
#define CP_WAIT0()   asm volatile("cp.async.wait_group 0;" ::: "memory")
#define CP_WAIT1()   asm volatile("cp.async.wait_group 1;" ::: "memory")

__device__ __forceinline__ uint32_t packh2(float x, float y) {
    __half2 h = __floats2half2_rn(x, y);
    return *(uint32_t*)&h;
}

// Swizzled byte offset for chunk (row, c) of a [rows][32]-fp16 tile.
__device__ __forceinline__ uint32_t tile_off(int row, int c) {
    const int pr = row >> 1;
    const int ch = ((row & 1) << 2) | c;
    return (uint32_t)(pr * 128 + ((ch ^ (pr & 7)) << 4));
}

// ---------------------------------------------------------------------------
// Weight preconversion (unchanged).
// ---------------------------------------------------------------------------
__global__ void __launch_bounds__(256)
wcvt(const float* __restrict__ Wq, const float* __restrict__ Wkv,
     const float* __restrict__ Wscale, const float* __restrict__ Wshift,
     const float* __restrict__ Wout)
{
    const int blk = blockIdx.x;
    const int mat = blk >> 3, kt = blk & 7;
    const float* srcs[6] = {Wscale, Wshift, Wq, Wkv, Wkv + 65536, Wout};
    const float* src = srcs[mat];
    uint8_t* dst = (uint8_t*)g_wh + (size_t)blk * 16384;
    for (int i = threadIdx.x; i < 8192; i += 256) {
        const int r = i >> 5, col = i & 31;
        const __half h = __float2half_rn(src[r * 256 + kt * 32 + col]);
        *(__half*)(dst + tile_off(r, col >> 3) + (col & 7) * 2) = h;
    }
}

// ---------------------------------------------------------------------------
// Fused projection v6: 512 threads. KC=64 (4 k-steps/phase, 20 total),
// 3-deep weight ring with wait_group 1 (fetch 2 steps ahead).
// scale/shift held fp16 in smem.
// smem map (1024-aligned base):
//  XT 0..32KB | CT 32..64KB | Wring 64..160KB (3x32KB) |
//  SC 160..192KB (fp16 [64][256]) | SH 192..224KB
// ---------------------------------------------------------------------------
#define FP_SMEM (229376 + 1024)

__global__ void __launch_bounds__(512, 1)
fused_proj(const float* __restrict__ x, const float* __restrict__ ctx,
           __half* __restrict__ outq, __half* __restrict__ outk,
           __half* __restrict__ outv)
{
    extern __shared__ uint8_t smraw[];
    const uint32_t base = (smem_u32(smraw) + 1023u) & ~1023u;
    const uint32_t XT  = base;
    const uint32_t CT  = base + 32768;
    const uint32_t WR  = base + 65536;    // 3 x 32KB ring
    const uint32_t SC  = base + 163840;   // fp16 [64][256]
    const uint32_t SH  = base + 196608;

    const int tid = threadIdx.x, wid = tid >> 5, lane = tid & 31;
    const int m0 = blockIdx.x * 64;
    const int warp_m = (wid & 3) * 16;   // 4 warps down M (64)
    const int warp_n = (wid >> 2) * 64;  // 4 warps across N (256)

    // ---- Stage x & ctx tiles: 64 rows x 256 fp32 -> fp16 chunk-major ----
    {
        const float* xp = x   + (size_t)m0 * CDIM;
        const float* cp = ctx + (size_t)m0 * CDIM;
        #pragma unroll
        for (int i = 0; i < 4; i++) {
            const int unit = i * 512 + tid;       // 2048 units of 8 floats
            const int row = unit >> 5, u = unit & 31;
            const int kc = u >> 2, c = u & 3;
            const uint32_t so = (uint32_t)(kc * 4096) + tile_off(row, c);
            const float4* p = (const float4*)(xp + row * CDIM + u * 8);
            float4 f0 = p[0], f1 = p[1];
            uint4 v;
            v.x = packh2(f0.x, f0.y); v.y = packh2(f0.z, f0.w);
            v.z = packh2(f1.x, f1.y); v.w = packh2(f1.z, f1.w);
            asm volatile("st.shared.v4.b32 [%0], {%1,%2,%3,%4};" ::
                "r"(XT + so), "r"(v.x), "r"(v.y), "r"(v.z), "r"(v.w) : "memory");
            p = (const float4*)(cp + row * CDIM + u * 8);
            f0 = p[0]; f1 = p[1];
            v.x = packh2(f0.x, f0.y); v.y = packh2(f0.z, f0.w);
            v.z = packh2(f1.x, f1.y); v.w = packh2(f1.z, f1.w);
            asm volatile("st.shared.v4.b32 [%0], {%1,%2,%3,%4};" ::
                "r"(CT + so), "r"(v.x), "r"(v.y), "r"(v.z), "r"(v.w) : "memory");
        }
    }
    __syncthreads();

    // cp.async weight stage: 32KB (= blocks 2*st, 2*st+1 of mat), 512 x 64B.
    auto ldw_async = [&](int mat, int st) {
        const uint8_t* src = (const uint8_t*)g_wh
                           + ((size_t)(mat * 8 + st * 2) << 14) + tid * 64;
        const uint32_t d0 = WR + (uint32_t)(st % 3) * 32768 + tid * 64;
        CP_ASYNC16(d0,      src);
        CP_ASYNC16(d0 + 16, src + 16);
        CP_ASYNC16(d0 + 32, src + 32);
        CP_ASYNC16(d0 + 48, src + 48);
        CP_COMMIT();
    };

    float d[8][4];
    auto do_gemm = [&](int mat, uint32_t at) {
        #pragma unroll
        for (int nt = 0; nt < 8; nt++)
            #pragma unroll
            for (int i = 0; i < 4; i++) d[nt][i] = 0.f;
        ldw_async(mat, 0);
        ldw_async(mat, 1);
        #pragma unroll 1
        for (int kt = 0; kt < 4; kt++) {
            if (kt < 3) CP_WAIT1(); else CP_WAIT0();   // stage kt landed
            __syncthreads();          // all warps past step kt-1 MMAs
            if (kt < 2) ldw_async(mat, kt + 2);
            const uint32_t wbase = WR + (uint32_t)(kt % 3) * 32768;
            #pragma unroll
            for (int sub = 0; sub < 2; sub++) {
                const uint32_t wb = wbase + sub * 16384;
                const uint32_t ac = at + (kt * 2 + sub) * 4096;
                #pragma unroll
                for (int s = 0; s < 2; s++) {
                    uint32_t a[4];
                    const int R = warp_m + (lane & 15);
                    const int c = s * 2 + (lane >> 4);
                    LDSM_X4(a[0], a[1], a[2], a[3], ac + tile_off(R, c));
                    #pragma unroll
                    for (int np = 0; np < 4; np++) {
                        const int g = lane >> 3, lr = lane & 7;
                        const int Rn = warp_n + np * 16 + ((g >> 1) << 3) + lr;
                        const int cb = s * 2 + (g & 1);
                        uint32_t b[4];
                        LDSM_X4(b[0], b[1], b[2], b[3], wb + tile_off(Rn, cb));
                        MMA16816(d[np * 2 + 0], a, b[0], b[1]);
                        MMA16816(d[np * 2 + 1], a, b[2], b[3]);
                    }
                }
            }
        }
    };

    // fp16 [64][256] smem: pair-index shifted for conflict-free quads.
    auto smoff16 = [&](int row, int col) -> uint32_t {
        const int cpp = ((col >> 1) + row * 4) & 127;
        return (uint32_t)(row * 512 + cpp * 4);
    };

    // ---- scale, shift (from ctx tile) -> fp16 smem ----
    const uint32_t Sm[2] = {SC, SH};
    #pragma unroll 1
    for (int mphase = 0; mphase < 2; mphase++) {
        do_gemm(mphase, CT);                 // mat 0=Wscale, 1=Wshift
        #pragma unroll
        for (int half = 0; half < 2; half++) {
            const int row = warp_m + (lane >> 2) + half * 8;
            #pragma unroll
            for (int nt = 0; nt < 8; nt++) {
                const int col = warp_n + nt * 8 + (lane & 3) * 2;
                asm volatile("st.shared.b32 [%0], %1;" ::
                    "r"(Sm[mphase] + smoff16(row, col)),
                    "r"(packh2(d[nt][half * 2 + 0], d[nt][half * 2 + 1])) : "memory");
            }
        }
        __syncthreads();
    }

    // ---- q, k, v (from x tile) with fused FiLM; fp16 stores ----
    __half* Outs[3] = {outq, outk, outv};
    #pragma unroll 1
    for (int mphase = 0; mphase < 3; mphase++) {
        do_gemm(2 + mphase, XT);             // mats 2=Wq, 3=Wk, 4=Wv
        __half* outp = Outs[mphase];
        #pragma unroll
        for (int half = 0; half < 2; half++) {
            const int row = warp_m + (lane >> 2) + half * 8;
            const size_t rbase = (size_t)(m0 + row) * CDIM;
            #pragma unroll
            for (int nt = 0; nt < 8; nt++) {
                const int col = warp_n + nt * 8 + (lane & 3) * 2;
                uint32_t sb, tb;
                asm volatile("ld.shared.b32 %0, [%1];"
                    : "=r"(sb) : "r"(SC + smoff16(row, col)));
                asm volatile("ld.shared.b32 %0, [%1];"
                    : "=r"(tb) : "r"(SH + smoff16(row, col)));
                const float2 sf = __half22float2(*(__half2*)&sb);
                const float2 tf = __half22float2(*(__half2*)&tb);
                const float vx = fmaf(sf.x, d[nt][half * 2 + 0], tf.x);
                const float vy = fmaf(sf.y, d[nt][half * 2 + 1], tf.y);
                *(uint32_t*)(outp + rbase + col) = packh2(vx, vy);
            }
        }
        __syncthreads();
    }
}

// ---------------------------------------------------------------------------
// Out-projection GEMM (unchanged from R11): out = A @ Wout^T, K=256.
// ---------------------------------------------------------------------------
__global__ void __launch_bounds__(256)
gemm_h16(const __half* __restrict__ A, float* __restrict__ out)
{
    __shared__ alignas(128) uint8_t sA[2][8192];
    __shared__ alignas(128) uint8_t sB[2][8192];

    const int tid  = threadIdx.x;
    const int wid  = tid >> 5;
    const int lane = tid & 31;
    const int m0 = blockIdx.y * 128;
    const int n0 = blockIdx.x * 128;

    const int warp_m = (wid & 3) * 32;
    const int warp_n = (wid >> 2) * 64;

    const uint32_t sa0 = smem_u32(&sA[0][0]);
    const uint32_t sa1 = smem_u32(&sA[1][0]);
    const uint32_t sb0 = smem_u32(&sB[0][0]);
    const uint32_t sb1 = smem_u32(&sB[1][0]);

    float d[2][8][4];
    #pragma unroll
    for (int mt = 0; mt < 2; mt++)
        #pragma unroll
        for (int nt = 0; nt < 8; nt++)
            #pragma unroll
            for (int i = 0; i < 4; i++) d[mt][nt][i] = 0.f;

    auto ldab_async = [&](int kt, uint32_t abuf, uint32_t bbuf) {
        #pragma unroll
        for (int u = 0; u < 2; u++) {
            const int idx = tid + u * 256;
            const int row = idx >> 2, c = idx & 3;
            const __half* src = A + (size_t)(m0 + row) * CDIM + kt * 32 + c * 8;
            CP_ASYNC16(abuf + tile_off(row, c), src);
        }
        const uint8_t* bsrc = (const uint8_t*)g_wh + ((size_t)(40 + kt) << 14)
                            + n0 * 64 + tid * 32;
        const uint32_t d0 = bbuf + tid * 32;
        CP_ASYNC16(d0,      bsrc);
        CP_ASYNC16(d0 + 16, bsrc + 16);
        CP_COMMIT();
    };

    ldab_async(0, sa0, sb0);

    #pragma unroll 1
    for (int kt = 0; kt < 8; kt++) {
        CP_WAIT0();
        __syncthreads();
        if (kt < 7) ldab_async(kt + 1, (kt & 1) ? sa0 : sa1, (kt & 1) ? sb0 : sb1);
        const uint32_t abuf = (kt & 1) ? sa1 : sa0;
        const uint32_t bbuf = (kt & 1) ? sb1 : sb0;

        #pragma unroll
        for (int s = 0; s < 2; s++) {
            uint32_t a[2][4];
            #pragma unroll
            for (int mt = 0; mt < 2; mt++) {
                const int R = warp_m + mt * 16 + (lane & 15);
                const int c = s * 2 + (lane >> 4);
                LDSM_X4(a[mt][0], a[mt][1], a[mt][2], a[mt][3],
                        abuf + tile_off(R, c));
            }
            #pragma unroll
            for (int np = 0; np < 4; np++) {
                const int g = lane >> 3, lr = lane & 7;
                const int Rn = warp_n + np * 16 + ((g >> 1) << 3) + lr;
                const int c = s * 2 + (g & 1);
                uint32_t b[4];
                LDSM_X4(b[0], b[1], b[2], b[3], bbuf + tile_off(Rn, c));
                #pragma unroll
                for (int mt = 0; mt < 2; mt++) {
                    MMA16816(d[mt][np * 2 + 0], a[mt], b[0], b[1]);
                    MMA16816(d[mt][np * 2 + 1], a[mt], b[2], b[3]);
                }
            }
        }
    }

    #pragma unroll
    for (int mt = 0; mt < 2; mt++) {
        #pragma unroll
        for (int half = 0; half < 2; half++) {
            const int row = m0 + warp_m + mt * 16 + (lane >> 2) + half * 8;
            const size_t rbase = (size_t)row * CDIM;
            #pragma unroll
            for (int nt = 0; nt < 8; nt++) {
                const int col = n0 + warp_n + nt * 8 + (lane & 3) * 2;
                float2 v;
                v.x = d[mt][nt][half * 2 + 0];
                v.y = d[mt][nt][half * 2 + 1];
                *(float2*)(out + rbase + col) = v;
            }
        }
    }
}

// ---------------------------------------------------------------------------
// Tensor-core attention (unchanged from R11): fp16 in/out.
// ---------------------------------------------------------------------------
#define AT_SMEM (57344 + 1024)

__global__ void __launch_bounds__(128)
attn_mma(const __half* __restrict__ Qg, const __half* __restrict__ Kg,
         const __half* __restrict__ Vg, __half* __restrict__ O)
{
    extern __shared__ uint8_t smraw[];
    const uint32_t base = (smem_u32(smraw) + 1023u) & ~1023u;
    const uint32_t SQ = base;
    const uint32_t SK = base + 8192;
    const uint32_t SVT = base + 16384;
    const uint32_t SP = base + 24576;

    const int tid = threadIdx.x, wid = tid >> 5, lane = tid & 31;
    const int bh = blockIdx.x;
    const size_t r0 = (size_t)(bh >> 3) * 128;
    const int c0 = (bh & 7) * 32;
    const int warp_m = wid * 32;

    {
        const int part = tid & 3;
        #pragma unroll
        for (int pass = 0; pass < 4; pass++) {
            const int row = (tid >> 2) + pass * 32;
            const uint4 qv = *(const uint4*)(Qg + (r0 + row) * CDIM + c0 + part * 8);
            asm volatile("st.shared.v4.b32 [%0], {%1,%2,%3,%4};" ::
                "r"(SQ + tile_off(row, part)), "r"(qv.x), "r"(qv.y), "r"(qv.z), "r"(qv.w) : "memory");
            const uint4 kv = *(const uint4*)(Kg + (r0 + row) * CDIM + c0 + part * 8);
            asm volatile("st.shared.v4.b32 [%0], {%1,%2,%3,%4};" ::
                "r"(SK + tile_off(row, part)), "r"(kv.x), "r"(kv.y), "r"(kv.z), "r"(kv.w) : "memory");
        }
        #pragma unroll
        for (int pass = 0; pass < 4; pass++) {
            const int j = (tid >> 2) + pass * 32;
            const int e0 = part * 8;
            const uint4 vv = *(const uint4*)(Vg + (r0 + j) * CDIM + c0 + e0);
            const uint16_t* hw = (const uint16_t*)&vv;
            const uint32_t cb = SVT + (j >> 5) * 2048;
            const int jc = j & 31;
            #pragma unroll
            for (int i = 0; i < 8; i++) {
                asm volatile("st.shared.b16 [%0], %1;" ::
                    "r"(cb + tile_off(e0 + i, jc >> 3) + (jc & 7) * 2), "h"(hw[i]) : "memory");
            }
        }
    }
    __syncthreads();

    float d[2][16][4];
    #pragma unroll
    for (int mt = 0; mt < 2; mt++)
        #pragma unroll
        for (int nt = 0; nt < 16; nt++)
            #pragma unroll
            for (int i = 0; i < 4; i++) d[mt][nt][i] = 0.f;

    #pragma unroll
    for (int s = 0; s < 2; s++) {
        uint32_t a[2][4];
        #pragma unroll
        for (int mt = 0; mt < 2; mt++) {
            const int R = warp_m + mt * 16 + (lane & 15);
            const int c = s * 2 + (lane >> 4);
            LDSM_X4(a[mt][0], a[mt][1], a[mt][2], a[mt][3], SQ + tile_off(R, c));
        }
        #pragma unroll
        for (int np = 0; np < 8; np++) {
            const int g = lane >> 3, lr = lane & 7;
            const int Rn = np * 16 + ((g >> 1) << 3) + lr;
            const int c = s * 2 + (g & 1);
            uint32_t b[4];
            LDSM_X4(b[0], b[1], b[2], b[3], SK + tile_off(Rn, c));
            #pragma unroll
            for (int mt = 0; mt < 2; mt++) {
                MMA16816(d[mt][np * 2 + 0], a[mt], b[0], b[1]);
                MMA16816(d[mt][np * 2 + 1], a[mt], b[2], b[3]);
            }
        }
    }

    const float sc = 0.17677669529663687f;
    float inv[2][2];
    #pragma unroll
    for (int mt = 0; mt < 2; mt++) {
        #pragma unroll
        for (int half = 0; half < 2; half++) {
            float mx = -1e30f;
            #pragma unroll
            for (int nt = 0; nt < 16; nt++) {
                mx = fmaxf(mx, fmaxf(d[mt][nt][half * 2], d[mt][nt][half * 2 + 1]));
            }
            mx = fmaxf(mx, __shfl_xor_sync(0xffffffffu, mx, 1));
            mx = fmaxf(mx, __shfl_xor_sync(0xffffffffu, mx, 2));
            const float mxs = mx * sc;
            float sum = 0.f;
            const int row = warp_m + mt * 16 + (lane >> 2) + half * 8;
            #pragma unroll
            for (int nt = 0; nt < 16; nt++) {
                const float p0 = __expf(fmaf(d[mt][nt][half * 2 + 0], sc, -mxs));
                const float p1 = __expf(fmaf(d[mt][nt][half * 2 + 1], sc, -mxs));
                sum += p0 + p1;
                const int jc = (nt & 3) * 8 + (lane & 3) * 2;
                asm volatile("st.shared.b32 [%0], %1;" ::
                    "r"(SP + (nt >> 2) * 8192 + tile_off(row, jc >> 3) + (jc & 7) * 2),
                    "r"(packh2(p0, p1)) : "memory");
            }
            sum += __shfl_xor_sync(0xffffffffu, sum, 1);
            sum += __shfl_xor_sync(0xffffffffu, sum, 2);
            inv[mt][half] = 1.f / sum;
        }
    }
    __syncwarp();

    float o[2][4][4];
    #pragma unroll
    for (int mt = 0; mt < 2; mt++)
        #pragma unroll
        for (int nt = 0; nt < 4; nt++)
            #pragma unroll
            for (int i = 0; i < 4; i++) o[mt][nt][i] = 0.f;

    #pragma unroll
    for (int ck = 0; ck < 4; ck++) {
        const uint32_t pb = SP + ck * 8192;
        const uint32_t vb = SVT + ck * 2048;
        #pragma unroll
        for (int s = 0; s < 2; s++) {
            uint32_t a[2][4];
            #pragma unroll
            for (int mt = 0; mt < 2; mt++) {
                const int R = warp_m + mt * 16 + (lane & 15);
                const int c = s * 2 + (lane >> 4);
                LDSM_X4(a[mt][0], a[mt][1], a[mt][2], a[mt][3], pb + tile_off(R, c));
            }
            #pragma unroll
            for (int np = 0; np < 2; np++) {
                const int g = lane >> 3, lr = lane & 7;
                const int Rn = np * 16 + ((g >> 1) << 3) + lr;
                const int c = s * 2 + (g & 1);
                uint32_t b[4];
                LDSM_X4(b[0], b[1], b[2], b[3], vb + tile_off(Rn, c));
                #pragma unroll
                for (int mt = 0; mt < 2; mt++) {
                    MMA16816(o[mt][np * 2 + 0], a[mt], b[0], b[1]);
                    MMA16816(o[mt][np * 2 + 1], a[mt], b[2], b[3]);
                }
            }
        }
    }

    #pragma unroll
    for (int mt = 0; mt < 2; mt++) {
        #pragma unroll
        for (int half = 0; half < 2; half++) {
            const int row = warp_m + mt * 16 + (lane >> 2) + half * 8;
            const float iv = inv[mt][half];
            const size_t rbase = (r0 + row) * CDIM + c0;
            #pragma unroll
            for (int nt = 0; nt < 4; nt++) {
                const int col = nt * 8 + (lane & 3) * 2;
                *(uint32_t*)(O + rbase + col) =
                    packh2(o[mt][nt][half * 2 + 0] * iv,
                           o[mt][nt][half * 2 + 1] * iv);
            }
        }
    }
}

// ---------------------------------------------------------------------------
// Launch
// ---------------------------------------------------------------------------
extern "C" void kernel_launch(void* const* d_in, const int* in_sizes, int n_in,
                              void* d_out, int out_size)
{
    const float* x      = (const float*)d_in[0];
    const float* ctx    = (const float*)d_in[1];
    const float* Wq     = (const float*)d_in[2];
    const float* Wkv    = (const float*)d_in[3];
    const float* Wout   = (const float*)d_in[4];
    const float* Wscale = (const float*)d_in[5];
    const float* Wshift = (const float*)d_in[6];
    float* out = (float*)d_out;

    __half *gq, *gk, *gv, *ga;
    cudaGetSymbolAddress((void**)&gq, g_q);
    cudaGetSymbolAddress((void**)&gk, g_k);
    cudaGetSymbolAddress((void**)&gv, g_v);
    cudaGetSymbolAddress((void**)&ga, g_attn);

    cudaFuncSetAttribute(fused_proj,
                         cudaFuncAttributeMaxDynamicSharedMemorySize, FP_SMEM);
    cudaFuncSetAttribute(attn_mma,
                         cudaFuncAttributeMaxDynamicSharedMemorySize, AT_SMEM);

    wcvt<<<48, 256>>>(Wq, Wkv, Wscale, Wshift, Wout);
    fused_proj<<<MROWS / 64, 512, FP_SMEM>>>(x, ctx, gq, gk, gv);
    attn_mma<<<8192, 128, AT_SMEM>>>(gq, gk, gv, ga);
    gemm_h16<<<dim3(2, 1024), 256>>>(ga, out);
}

// round 14
// speedup vs baseline: 1.1516x; 1.1516x over previous
#include <cuda_runtime.h>
#include <cuda_fp16.h>
#include <cstdint>
#include <math.h>

// Fixed shapes: B=8, C=256, H=128, W=128, heads=8, e=32
#define MROWS 131072
#define CDIM  256
#define NELEM (MROWS * CDIM)

// Scratch (allocation-free rule: __device__ globals). All fp16.
__device__ __align__(16) __half g_q[NELEM];
__device__ __align__(16) __half g_k[NELEM];
__device__ __align__(16) __half g_v[NELEM];
__device__ __align__(16) __half g_attn[NELEM];
__device__ __align__(16) __half g_s[NELEM];    // scale (fp16)
__device__ __align__(16) __half g_h[NELEM];    // shift (fp16)
// Preconverted fp16 weights, swizzled chunk-major:
// 6 mats x 8 ksteps x [256 rows][32 cols] fp16 (16KB blocks)
// mats: 0=Wscale 1=Wshift 2=Wq 3=Wk 4=Wv 5=Wout
__device__ __align__(16) uint16_t g_wh[6 * 8 * 8192];

// ---------------------------------------------------------------------------
// PTX helpers
// ---------------------------------------------------------------------------
__device__ __forceinline__ uint32_t smem_u32(const void* p) {
    uint32_t a;
    asm("{ .reg .u64 t; cvta.to.shared.u64 t, %1; cvt.u32.u64 %0, t; }"
        : "=r"(a) : "l"(p));
    return a;
}

#define LDSM_X4(r0, r1, r2, r3, addr)                                         \
    asm volatile("ldmatrix.sync.aligned.m8n8.x4.shared.b16 {%0,%1,%2,%3}, [%4];" \
                 : "=r"(r0), "=r"(r1), "=r"(r2), "=r"(r3) : "r"(addr))

#define MMA16816(d, a, b0, b1)                                                \
    asm volatile("mma.sync.aligned.m16n8k16.row.col.f32.f16.f16.f32 "         \
                 "{%0,%1,%2,%3}, {%4,%5,%6,%7}, {%8,%9}, {%0,%1,%2,%3};"      \
                 : "+f"((d)[0]), "+f"((d)[1]), "+f"((d)[2]), "+f"((d)[3])     \
                 : "r"((a)[0]), "r"((a)[1]), "r"((a)[2]), "r"((a)[3]),        \
                   "r"(b0), "r"(b1))

#define CP_ASYNC16(dst, src)                                                  \
    asm volatile("cp.async.cg.shared.global [%0], [%1], 16;" ::               \
                 "r"(dst), "l"(src) : "memory")
#define CP_COMMIT()  asm volatile("cp.async.commit_group;" ::: "memory")
#define CP_WAIT0()   asm volatile("cp.async.wait_group 0;" ::: "memory")

__device__ __forceinline__ uint32_t packh2(float x, float y) {
    __half2 h = __floats2half2_rn(x, y);
    return *(uint32_t*)&h;
}

// Swizzled byte offset for chunk (row, c) of a [rows][32]-fp16 tile.
__device__ __forceinline__ uint32_t tile_off(int row, int c) {
    const int pr = row >> 1;
    const int ch = ((row & 1) << 2) | c;
    return (uint32_t)(pr * 128 + ((ch ^ (pr & 7)) << 4));
}

// ---------------------------------------------------------------------------
// Weight preconversion: fp32 -> fp16 swizzled chunk-major (unchanged).
// ---------------------------------------------------------------------------
__global__ void __launch_bounds__(256)
wcvt(const float* __restrict__ Wq, const float* __restrict__ Wkv,
     const float* __restrict__ Wscale, const float* __restrict__ Wshift,
     const float* __restrict__ Wout)
{
    const int blk = blockIdx.x;
    const int mat = blk >> 3, kt = blk & 7;
    const float* srcs[6] = {Wscale, Wshift, Wq, Wkv, Wkv + 65536, Wout};
    const float* src = srcs[mat];
    uint8_t* dst = (uint8_t*)g_wh + (size_t)blk * 16384;
    for (int i = threadIdx.x; i < 8192; i += 256) {
        const int r = i >> 5, col = i & 31;
        const __half h = __float2half_rn(src[r * 256 + kt * 32 + col]);
        *(__half*)(dst + tile_off(r, col >> 3) + (col & 7) * 2) = h;
    }
}

// ===========================================================================
// Multi-mat projection kernel skeleton (gemm_h16 shape):
// grid (2, 1024), 256 thr, warp grid 4(M)x2(N). A tile [128][256] fp16 staged
// once in smem; NMATS weight mats stream as a single linear cp.async pipeline
// over blocks [matBase*8, matBase*8 + NMATS*8) of g_wh.
// smem: AT 64KB (8 chunks x 8KB) + B ring 2 x 8KB = 80KB -> 2 CTAs/SM.
// ===========================================================================
#define PROJ_SMEM (65536 + 16384 + 1024)

// ---- scale/shift producer: mats {0,1}, fp16 epilogue to g_s/g_h ----
__global__ void __launch_bounds__(256, 2)
gemm_ss(const float* __restrict__ ctx, __half* __restrict__ outS,
        __half* __restrict__ outH)
{
    extern __shared__ uint8_t smraw[];
    const uint32_t AT = (smem_u32(smraw) + 1023u) & ~1023u;
    const uint32_t B0 = AT + 65536;
    const uint32_t B1 = B0 + 8192;

    const int tid = threadIdx.x, wid = tid >> 5, lane = tid & 31;
    const int m0 = blockIdx.y * 128;
    const int n0 = blockIdx.x * 128;
    const int warp_m = (wid & 3) * 32;
    const int warp_n = (wid >> 2) * 64;

    // Stage A = ctx[m0..m0+128) rows, fp32 -> fp16 chunk-major (8 x 8KB).
    {
        const float* ap = ctx + (size_t)m0 * CDIM;
        #pragma unroll
        for (int i = 0; i < 16; i++) {
            const int unit = i * 256 + tid;        // 4096 units of 8 floats
            const int row = unit >> 5, u = unit & 31;
            const int kc = u >> 2, c = u & 3;
            const float4* p = (const float4*)(ap + row * CDIM + u * 8);
            const float4 f0 = p[0], f1 = p[1];
            uint4 v;
            v.x = packh2(f0.x, f0.y); v.y = packh2(f0.z, f0.w);
            v.z = packh2(f1.x, f1.y); v.w = packh2(f1.z, f1.w);
            asm volatile("st.shared.v4.b32 [%0], {%1,%2,%3,%4};" ::
                "r"(AT + kc * 8192 + tile_off(row, c)),
                "r"(v.x), "r"(v.y), "r"(v.z), "r"(v.w) : "memory");
        }
    }

    // B stage: 8KB = rows [n0, n0+128) of g_wh block (matBase*8 + step).
    auto ldb = [&](int step, uint32_t buf) {
        const uint8_t* src = (const uint8_t*)g_wh + ((size_t)(0 * 8 + step) << 14)
                           + n0 * 64 + tid * 32;
        const uint32_t d0 = buf + tid * 32;
        CP_ASYNC16(d0,      src);
        CP_ASYNC16(d0 + 16, src + 16);
        CP_COMMIT();
    };

    float d[2][8][4];
    #pragma unroll
    for (int mt = 0; mt < 2; mt++)
        #pragma unroll
        for (int nt = 0; nt < 8; nt++)
            #pragma unroll
            for (int i = 0; i < 4; i++) d[mt][nt][i] = 0.f;

    ldb(0, B0);
    __half* Outs[2] = {outS, outH};

    #pragma unroll 1
    for (int step = 0; step < 16; step++) {
        CP_WAIT0();
        __syncthreads();
        if (step < 15) ldb(step + 1, (step & 1) ? B0 : B1);
        const uint32_t bbuf = (step & 1) ? B1 : B0;
        const uint32_t ac = AT + (step & 7) * 8192;

        #pragma unroll
        for (int ks = 0; ks < 2; ks++) {
            uint32_t a[2][4];
            #pragma unroll
            for (int mt = 0; mt < 2; mt++) {
                const int R = warp_m + mt * 16 + (lane & 15);
                const int c = ks * 2 + (lane >> 4);
                LDSM_X4(a[mt][0], a[mt][1], a[mt][2], a[mt][3],
                        ac + tile_off(R, c));
            }
            #pragma unroll
            for (int np = 0; np < 4; np++) {
                const int g = lane >> 3, lr = lane & 7;
                const int Rn = warp_n + np * 16 + ((g >> 1) << 3) + lr;
                const int c = ks * 2 + (g & 1);
                uint32_t b[4];
                LDSM_X4(b[0], b[1], b[2], b[3], bbuf + tile_off(Rn, c));
                #pragma unroll
                for (int mt = 0; mt < 2; mt++) {
                    MMA16816(d[mt][np * 2 + 0], a[mt], b[0], b[1]);
                    MMA16816(d[mt][np * 2 + 1], a[mt], b[2], b[3]);
                }
            }
        }

        if ((step & 7) == 7) {                      // mat boundary: epilogue
            __half* outp = Outs[step >> 3];
            #pragma unroll
            for (int mt = 0; mt < 2; mt++)
                #pragma unroll
                for (int half = 0; half < 2; half++) {
                    const int row = m0 + warp_m + mt * 16 + (lane >> 2) + half * 8;
                    const size_t rbase = (size_t)row * CDIM;
                    #pragma unroll
                    for (int nt = 0; nt < 8; nt++) {
                        const int col = n0 + warp_n + nt * 8 + (lane & 3) * 2;
                        *(uint32_t*)(outp + rbase + col) =
                            packh2(d[mt][nt][half * 2 + 0],
                                   d[mt][nt][half * 2 + 1]);
                    }
                }
            if (step < 15) {
                #pragma unroll
                for (int mt = 0; mt < 2; mt++)
                    #pragma unroll
                    for (int nt = 0; nt < 8; nt++)
                        #pragma unroll
                        for (int i = 0; i < 4; i++) d[mt][nt][i] = 0.f;
            }
        }
    }
}

// ---- q/k/v producer: mats {2,3,4}, FiLM epilogue from g_s/g_h ----
__global__ void __launch_bounds__(256, 2)
gemm_qkv(const float* __restrict__ x, const __half* __restrict__ S,
         const __half* __restrict__ Hs,
         __half* __restrict__ outq, __half* __restrict__ outk,
         __half* __restrict__ outv)
{
    extern __shared__ uint8_t smraw[];
    const uint32_t AT = (smem_u32(smraw) + 1023u) & ~1023u;
    const uint32_t B0 = AT + 65536;
    const uint32_t B1 = B0 + 8192;

    const int tid = threadIdx.x, wid = tid >> 5, lane = tid & 31;
    const int m0 = blockIdx.y * 128;
    const int n0 = blockIdx.x * 128;
    const int warp_m = (wid & 3) * 32;
    const int warp_n = (wid >> 2) * 64;

    {
        const float* ap = x + (size_t)m0 * CDIM;
        #pragma unroll
        for (int i = 0; i < 16; i++) {
            const int unit = i * 256 + tid;
            const int row = unit >> 5, u = unit & 31;
            const int kc = u >> 2, c = u & 3;
            const float4* p = (const float4*)(ap + row * CDIM + u * 8);
            const float4 f0 = p[0], f1 = p[1];
            uint4 v;
            v.x = packh2(f0.x, f0.y); v.y = packh2(f0.z, f0.w);
            v.z = packh2(f1.x, f1.y); v.w = packh2(f1.z, f1.w);
            asm volatile("st.shared.v4.b32 [%0], {%1,%2,%3,%4};" ::
                "r"(AT + kc * 8192 + tile_off(row, c)),
                "r"(v.x), "r"(v.y), "r"(v.z), "r"(v.w) : "memory");
        }
    }

    // Linear pipeline over blocks 16..39 (Wq, Wk, Wv).
    auto ldb = [&](int step, uint32_t buf) {
        const uint8_t* src = (const uint8_t*)g_wh + ((size_t)(16 + step) << 14)
                           + n0 * 64 + tid * 32;
        const uint32_t d0 = buf + tid * 32;
        CP_ASYNC16(d0,      src);
        CP_ASYNC16(d0 + 16, src + 16);
        CP_COMMIT();
    };

    float d[2][8][4];
    #pragma unroll
    for (int mt = 0; mt < 2; mt++)
        #pragma unroll
        for (int nt = 0; nt < 8; nt++)
            #pragma unroll
            for (int i = 0; i < 4; i++) d[mt][nt][i] = 0.f;

    ldb(0, B0);
    __half* Outs[3] = {outq, outk, outv};

    #pragma unroll 1
    for (int step = 0; step < 24; step++) {
        CP_WAIT0();
        __syncthreads();
        if (step < 23) ldb(step + 1, (step & 1) ? B0 : B1);
        const uint32_t bbuf = (step & 1) ? B1 : B0;
        const uint32_t ac = AT + (step & 7) * 8192;

        #pragma unroll
        for (int ks = 0; ks < 2; ks++) {
            uint32_t a[2][4];
            #pragma unroll
            for (int mt = 0; mt < 2; mt++) {
                const int R = warp_m + mt * 16 + (lane & 15);
                const int c = ks * 2 + (lane >> 4);
                LDSM_X4(a[mt][0], a[mt][1], a[mt][2], a[mt][3],
                        ac + tile_off(R, c));
            }
            #pragma unroll
            for (int np = 0; np < 4; np++) {
                const int g = lane >> 3, lr = lane & 7;
                const int Rn = warp_n + np * 16 + ((g >> 1) << 3) + lr;
                const int c = ks * 2 + (g & 1);
                uint32_t b[4];
                LDSM_X4(b[0], b[1], b[2], b[3], bbuf + tile_off(Rn, c));
                #pragma unroll
                for (int mt = 0; mt < 2; mt++) {
                    MMA16816(d[mt][np * 2 + 0], a[mt], b[0], b[1]);
                    MMA16816(d[mt][np * 2 + 1], a[mt], b[2], b[3]);
                }
            }
        }

        if ((step & 7) == 7) {                      // mat boundary: FiLM epi
            __half* outp = Outs[step >> 3];
            #pragma unroll
            for (int mt = 0; mt < 2; mt++)
                #pragma unroll
                for (int half = 0; half < 2; half++) {
                    const int row = m0 + warp_m + mt * 16 + (lane >> 2) + half * 8;
                    const size_t rbase = (size_t)row * CDIM;
                    #pragma unroll
                    for (int nt = 0; nt < 8; nt++) {
                        const int col = n0 + warp_n + nt * 8 + (lane & 3) * 2;
                        const uint32_t sb = *(const uint32_t*)(S  + rbase + col);
                        const uint32_t tb = *(const uint32_t*)(Hs + rbase + col);
                        const float2 sf = __half22float2(*(__half2*)&sb);
                        const float2 tf = __half22float2(*(__half2*)&tb);
                        const float vx = fmaf(sf.x, d[mt][nt][half * 2 + 0], tf.x);
                        const float vy = fmaf(sf.y, d[mt][nt][half * 2 + 1], tf.y);
                        *(uint32_t*)(outp + rbase + col) = packh2(vx, vy);
                    }
                }
            if (step < 23) {
                #pragma unroll
                for (int mt = 0; mt < 2; mt++)
                    #pragma unroll
                    for (int nt = 0; nt < 8; nt++)
                        #pragma unroll
                        for (int i = 0; i < 4; i++) d[mt][nt][i] = 0.f;
            }
        }
    }
}

// ---------------------------------------------------------------------------
// Out-projection GEMM (unchanged from R11): out = A @ Wout^T, K=256.
// ---------------------------------------------------------------------------
__global__ void __launch_bounds__(256)
gemm_h16(const __half* __restrict__ A, float* __restrict__ out)
{
    __shared__ alignas(128) uint8_t sA[2][8192];
    __shared__ alignas(128) uint8_t sB[2][8192];

    const int tid  = threadIdx.x;
    const int wid  = tid >> 5;
    const int lane = tid & 31;
    const int m0 = blockIdx.y * 128;
    const int n0 = blockIdx.x * 128;

    const int warp_m = (wid & 3) * 32;
    const int warp_n = (wid >> 2) * 64;

    const uint32_t sa0 = smem_u32(&sA[0][0]);
    const uint32_t sa1 = smem_u32(&sA[1][0]);
    const uint32_t sb0 = smem_u32(&sB[0][0]);
    const uint32_t sb1 = smem_u32(&sB[1][0]);

    float d[2][8][4];
    #pragma unroll
    for (int mt = 0; mt < 2; mt++)
        #pragma unroll
        for (int nt = 0; nt < 8; nt++)
            #pragma unroll
            for (int i = 0; i < 4; i++) d[mt][nt][i] = 0.f;

    auto ldab_async = [&](int kt, uint32_t abuf, uint32_t bbuf) {
        #pragma unroll
        for (int u = 0; u < 2; u++) {
            const int idx = tid + u * 256;
            const int row = idx >> 2, c = idx & 3;
            const __half* src = A + (size_t)(m0 + row) * CDIM + kt * 32 + c * 8;
            CP_ASYNC16(abuf + tile_off(row, c), src);
        }
        const uint8_t* bsrc = (const uint8_t*)g_wh + ((size_t)(40 + kt) << 14)
                            + n0 * 64 + tid * 32;
        const uint32_t d0 = bbuf + tid * 32;
        CP_ASYNC16(d0,      bsrc);
        CP_ASYNC16(d0 + 16, bsrc + 16);
        CP_COMMIT();
    };

    ldab_async(0, sa0, sb0);

    #pragma unroll 1
    for (int kt = 0; kt < 8; kt++) {
        CP_WAIT0();
        __syncthreads();
        if (kt < 7) ldab_async(kt + 1, (kt & 1) ? sa0 : sa1, (kt & 1) ? sb0 : sb1);
        const uint32_t abuf = (kt & 1) ? sa1 : sa0;
        const uint32_t bbuf = (kt & 1) ? sb1 : sb0;

        #pragma unroll
        for (int ks = 0; ks < 2; ks++) {
            uint32_t a[2][4];
            #pragma unroll
            for (int mt = 0; mt < 2; mt++) {
                const int R = warp_m + mt * 16 + (lane & 15);
                const int c = ks * 2 + (lane >> 4);
                LDSM_X4(a[mt][0], a[mt][1], a[mt][2], a[mt][3],
                        abuf + tile_off(R, c));
            }
            #pragma unroll
            for (int np = 0; np < 4; np++) {
                const int g = lane >> 3, lr = lane & 7;
                const int Rn = warp_n + np * 16 + ((g >> 1) << 3) + lr;
                const int c = ks * 2 + (g & 1);
                uint32_t b[4];
                LDSM_X4(b[0], b[1], b[2], b[3], bbuf + tile_off(Rn, c));
                #pragma unroll
                for (int mt = 0; mt < 2; mt++) {
                    MMA16816(d[mt][np * 2 + 0], a[mt], b[0], b[1]);
                    MMA16816(d[mt][np * 2 + 1], a[mt], b[2], b[3]);
                }
            }
        }
    }

    #pragma unroll
    for (int mt = 0; mt < 2; mt++) {
        #pragma unroll
        for (int half = 0; half < 2; half++) {
            const int row = m0 + warp_m + mt * 16 + (lane >> 2) + half * 8;
            const size_t rbase = (size_t)row * CDIM;
            #pragma unroll
            for (int nt = 0; nt < 8; nt++) {
                const int col = n0 + warp_n + nt * 8 + (lane & 3) * 2;
                float2 v;
                v.x = d[mt][nt][half * 2 + 0];
                v.y = d[mt][nt][half * 2 + 1];
                *(float2*)(out + rbase + col) = v;
            }
        }
    }
}

// ---------------------------------------------------------------------------
// Tensor-core attention (unchanged from R11): fp16 in/out.
// ---------------------------------------------------------------------------
#define AT_SMEM (57344 + 1024)

__global__ void __launch_bounds__(128)
attn_mma(const __half* __restrict__ Qg, const __half* __restrict__ Kg,
         const __half* __restrict__ Vg, __half* __restrict__ O)
{
    extern __shared__ uint8_t smraw[];
    const uint32_t base = (smem_u32(smraw) + 1023u) & ~1023u;
    const uint32_t SQ = base;
    const uint32_t SK = base + 8192;
    const uint32_t SVT = base + 16384;
    const uint32_t SP = base + 24576;

    const int tid = threadIdx.x, wid = tid >> 5, lane = tid & 31;
    const int bh = blockIdx.x;
    const size_t r0 = (size_t)(bh >> 3) * 128;
    const int c0 = (bh & 7) * 32;
    const int warp_m = wid * 32;

    {
        const int part = tid & 3;
        #pragma unroll
        for (int pass = 0; pass < 4; pass++) {
            const int row = (tid >> 2) + pass * 32;
            const uint4 qv = *(const uint4*)(Qg + (r0 + row) * CDIM + c0 + part * 8);
            asm volatile("st.shared.v4.b32 [%0], {%1,%2,%3,%4};" ::
                "r"(SQ + tile_off(row, part)), "r"(qv.x), "r"(qv.y), "r"(qv.z), "r"(qv.w) : "memory");
            const uint4 kv = *(const uint4*)(Kg + (r0 + row) * CDIM + c0 + part * 8);
            asm volatile("st.shared.v4.b32 [%0], {%1,%2,%3,%4};" ::
                "r"(SK + tile_off(row, part)), "r"(kv.x), "r"(kv.y), "r"(kv.z), "r"(kv.w) : "memory");
        }
        #pragma unroll
        for (int pass = 0; pass < 4; pass++) {
            const int j = (tid >> 2) + pass * 32;
            const int e0 = part * 8;
            const uint4 vv = *(const uint4*)(Vg + (r0 + j) * CDIM + c0 + e0);
            const uint16_t* hw = (const uint16_t*)&vv;
            const uint32_t cb = SVT + (j >> 5) * 2048;
            const int jc = j & 31;
            #pragma unroll
            for (int i = 0; i < 8; i++) {
                asm volatile("st.shared.b16 [%0], %1;" ::
                    "r"(cb + tile_off(e0 + i, jc >> 3) + (jc & 7) * 2), "h"(hw[i]) : "memory");
            }
        }
    }
    __syncthreads();

    float d[2][16][4];
    #pragma unroll
    for (int mt = 0; mt < 2; mt++)
        #pragma unroll
        for (int nt = 0; nt < 16; nt++)
            #pragma unroll
            for (int i = 0; i < 4; i++) d[mt][nt][i] = 0.f;

    #pragma unroll
    for (int s = 0; s < 2; s++) {
        uint32_t a[2][4];
        #pragma unroll
        for (int mt = 0; mt < 2; mt++) {
            const int R = warp_m + mt * 16 + (lane & 15);
            const int c = s * 2 + (lane >> 4);
            LDSM_X4(a[mt][0], a[mt][1], a[mt][2], a[mt][3], SQ + tile_off(R, c));
        }
        #pragma unroll
        for (int np = 0; np < 8; np++) {
            const int g = lane >> 3, lr = lane & 7;
            const int Rn = np * 16 + ((g >> 1) << 3) + lr;
            const int c = s * 2 + (g & 1);
            uint32_t b[4];
            LDSM_X4(b[0], b[1], b[2], b[3], SK + tile_off(Rn, c));
            #pragma unroll
            for (int mt = 0; mt < 2; mt++) {
                MMA16816(d[mt][np * 2 + 0], a[mt], b[0], b[1]);
                MMA16816(d[mt][np * 2 + 1], a[mt], b[2], b[3]);
            }
        }
    }

    const float sc = 0.17677669529663687f;
    float inv[2][2];
    #pragma unroll
    for (int mt = 0; mt < 2; mt++) {
        #pragma unroll
        for (int half = 0; half < 2; half++) {
            float mx = -1e30f;
            #pragma unroll
            for (int nt = 0; nt < 16; nt++) {
                mx = fmaxf(mx, fmaxf(d[mt][nt][half * 2], d[mt][nt][half * 2 + 1]));
            }
            mx = fmaxf(mx, __shfl_xor_sync(0xffffffffu, mx, 1));
            mx = fmaxf(mx, __shfl_xor_sync(0xffffffffu, mx, 2));
            const float mxs = mx * sc;
            float sum = 0.f;
            const int row = warp_m + mt * 16 + (lane >> 2) + half * 8;
            #pragma unroll
            for (int nt = 0; nt < 16; nt++) {
                const float p0 = __expf(fmaf(d[mt][nt][half * 2 + 0], sc, -mxs));
                const float p1 = __expf(fmaf(d[mt][nt][half * 2 + 1], sc, -mxs));
                sum += p0 + p1;
                const int jc = (nt & 3) * 8 + (lane & 3) * 2;
                asm volatile("st.shared.b32 [%0], %1;" ::
                    "r"(SP + (nt >> 2) * 8192 + tile_off(row, jc >> 3) + (jc & 7) * 2),
                    "r"(packh2(p0, p1)) : "memory");
            }
            sum += __shfl_xor_sync(0xffffffffu, sum, 1);
            sum += __shfl_xor_sync(0xffffffffu, sum, 2);
            inv[mt][half] = 1.f / sum;
        }
    }
    __syncwarp();

    float o[2][4][4];
    #pragma unroll
    for (int mt = 0; mt < 2; mt++)
        #pragma unroll
        for (int nt = 0; nt < 4; nt++)
            #pragma unroll
            for (int i = 0; i < 4; i++) o[mt][nt][i] = 0.f;

    #pragma unroll
    for (int ck = 0; ck < 4; ck++) {
        const uint32_t pb = SP + ck * 8192;
        const uint32_t vb = SVT + ck * 2048;
        #pragma unroll
        for (int s = 0; s < 2; s++) {
            uint32_t a[2][4];
            #pragma unroll
            for (int mt = 0; mt < 2; mt++) {
                const int R = warp_m + mt * 16 + (lane & 15);
                const int c = s * 2 + (lane >> 4);
                LDSM_X4(a[mt][0], a[mt][1], a[mt][2], a[mt][3], pb + tile_off(R, c));
            }
            #pragma unroll
            for (int np = 0; np < 2; np++) {
                const int g = lane >> 3, lr = lane & 7;
                const int Rn = np * 16 + ((g >> 1) << 3) + lr;
                const int c = s * 2 + (g & 1);
                uint32_t b[4];
                LDSM_X4(b[0], b[1], b[2], b[3], vb + tile_off(Rn, c));
                #pragma unroll
                for (int mt = 0; mt < 2; mt++) {
                    MMA16816(o[mt][np * 2 + 0], a[mt], b[0], b[1]);
                    MMA16816(o[mt][np * 2 + 1], a[mt], b[2], b[3]);
                }
            }
        }
    }

    #pragma unroll
    for (int mt = 0; mt < 2; mt++) {
        #pragma unroll
        for (int half = 0; half < 2; half++) {
            const int row = warp_m + mt * 16 + (lane >> 2) + half * 8;
            const float iv = inv[mt][half];
            const size_t rbase = (r0 + row) * CDIM + c0;
            #pragma unroll
            for (int nt = 0; nt < 4; nt++) {
                const int col = nt * 8 + (lane & 3) * 2;
                *(uint32_t*)(O + rbase + col) =
                    packh2(o[mt][nt][half * 2 + 0] * iv,
                           o[mt][nt][half * 2 + 1] * iv);
            }
        }
    }
}

// ---------------------------------------------------------------------------
// Launch
// ---------------------------------------------------------------------------
extern "C" void kernel_launch(void* const* d_in, const int* in_sizes, int n_in,
                              void* d_out, int out_size)
{
    const float* x      = (const float*)d_in[0];
    const float* ctx    = (const float*)d_in[1];
    const float* Wq     = (const float*)d_in[2];
    const float* Wkv    = (const float*)d_in[3];
    const float* Wout   = (const float*)d_in[4];
    const float* Wscale = (const float*)d_in[5];
    const float* Wshift = (const float*)d_in[6];
    float* out = (float*)d_out;

    __half *gq, *gk, *gv, *ga, *gs, *gh;
    cudaGetSymbolAddress((void**)&gq, g_q);
    cudaGetSymbolAddress((void**)&gk, g_k);
    cudaGetSymbolAddress((void**)&gv, g_v);
    cudaGetSymbolAddress((void**)&ga, g_attn);
    cudaGetSymbolAddress((void**)&gs, g_s);
    cudaGetSymbolAddress((void**)&gh, g_h);

    cudaFuncSetAttribute(gemm_ss,
                         cudaFuncAttributeMaxDynamicSharedMemorySize, PROJ_SMEM);
    cudaFuncSetAttribute(gemm_qkv,
                         cudaFuncAttributeMaxDynamicSharedMemorySize, PROJ_SMEM);
    cudaFuncSetAttribute(attn_mma,
                         cudaFuncAttributeMaxDynamicSharedMemorySize, AT_SMEM);

    wcvt<<<48, 256>>>(Wq, Wkv, Wscale, Wshift, Wout);
    gemm_ss<<<dim3(2, 1024), 256, PROJ_SMEM>>>(ctx, gs, gh);
    gemm_qkv<<<dim3(2, 1024), 256, PROJ_SMEM>>>(x, gs, gh, gq, gk, gv);
    attn_mma<<<8192, 128, AT_SMEM>>>(gq, gk, gv, ga);
    gemm_h16<<<dim3(2, 1024), 256>>>(ga, out);
}

// round 15
// speedup vs baseline: 1.4899x; 1.2937x over previous
#include <cuda_runtime.h>
#include <cuda_fp16.h>
#include <cstdint>
#include <math.h>

// Fixed shapes: B=8, C=256, H=128, W=128, heads=8, e=32
#define MROWS 131072
#define CDIM  256
#define NELEM (MROWS * CDIM)

// Scratch (allocation-free rule: __device__ globals)
__device__ __align__(16) __half g_q[NELEM];
__device__ __align__(16) __half g_k[NELEM];
__device__ __align__(16) __half g_v[NELEM];
__device__ __align__(16) __half g_attn[NELEM];
// Preconverted fp16 weights, swizzled chunk-major:
// 6 mats x 8 ksteps x [256 rows][32 cols] fp16 (16KB blocks)
// mats: 0=Wscale 1=Wshift 2=Wq 3=Wk 4=Wv 5=Wout
__device__ __align__(16) uint16_t g_wh[6 * 8 * 8192];

// ---------------------------------------------------------------------------
// PTX helpers
// ---------------------------------------------------------------------------
__device__ __forceinline__ uint32_t smem_u32(const void* p) {
    uint32_t a;
    asm("{ .reg .u64 t; cvta.to.shared.u64 t, %1; cvt.u32.u64 %0, t; }"
        : "=r"(a) : "l"(p));
    return a;
}

#define LDSM_X4(r0, r1, r2, r3, addr)                                         \
    asm volatile("ldmatrix.sync.aligned.m8n8.x4.shared.b16 {%0,%1,%2,%3}, [%4];" \
                 : "=r"(r0), "=r"(r1), "=r"(r2), "=r"(r3) : "r"(addr))

#define MMA16816(d, a, b0, b1)                                                \
    asm volatile("mma.sync.aligned.m16n8k16.row.col.f32.f16.f16.f32 "         \
                 "{%0,%1,%2,%3}, {%4,%5,%6,%7}, {%8,%9}, {%0,%1,%2,%3};"      \
                 : "+f"((d)[0]), "+f"((d)[1]), "+f"((d)[2]), "+f"((d)[3])     \
                 : "r"((a)[0]), "r"((a)[1]), "r"((a)[2]), "r"((a)[3]),        \
                   "r"(b0), "r"(b1))

#define CP_ASYNC16(dst, src)                                                  \
    asm volatile("cp.async.cg.shared.global [%0], [%1], 16;" ::               \
                 "r"(dst), "l"(src) : "memory")
#define CP_COMMIT()  asm volatile("cp.async.commit_group;" ::: "memory")
#define CP_WAIT0()   asm volatile("cp.async.wait_group 0;" ::: "memory")

__device__ __forceinline__ uint32_t packh2(float x, float y) {
    __half2 h = __floats2half2_rn(x, y);
    return *(uint32_t*)&h;
}

// Swizzled byte offset for chunk (row, c) of a [rows][32]-fp16 tile.
__device__ __forceinline__ uint32_t tile_off(int row, int c) {
    const int pr = row >> 1;
    const int ch = ((row & 1) << 2) | c;
    return (uint32_t)(pr * 128 + ((ch ^ (pr & 7)) << 4));
}

// ---------------------------------------------------------------------------
// Weight preconversion: fp32 -> fp16 in swizzled chunk-major layout.
// ---------------------------------------------------------------------------
__global__ void __launch_bounds__(256)
wcvt(const float* __restrict__ Wq, const float* __restrict__ Wkv,
     const float* __restrict__ Wscale, const float* __restrict__ Wshift,
     const float* __restrict__ Wout)
{
    const int blk = blockIdx.x;
    const int mat = blk >> 3, kt = blk & 7;
    const float* srcs[6] = {Wscale, Wshift, Wq, Wkv, Wkv + 65536, Wout};
    const float* src = srcs[mat];
    uint8_t* dst = (uint8_t*)g_wh + (size_t)blk * 16384;
    for (int i = threadIdx.x; i < 8192; i += 256) {
        const int r = i >> 5, col = i & 31;
        const __half h = __float2half_rn(src[r * 256 + kt * 32 + col]);
        *(__half*)(dst + tile_off(r, col >> 3) + (col & 7) * 2) = h;
    }
}

// ---------------------------------------------------------------------------
// Fused projection v5 (exact R11 form; best measured): 512 threads,
// KC=32 double-buffered cp.async weights, fp32 scale/shift in smem,
// fp16 q/k/v outputs.
// ---------------------------------------------------------------------------
#define FP_SMEM (229376 + 1024)

__global__ void __launch_bounds__(512, 1)
fused_proj(const float* __restrict__ x, const float* __restrict__ ctx,
           __half* __restrict__ outq, __half* __restrict__ outk,
           __half* __restrict__ outv)
{
    extern __shared__ uint8_t smraw[];
    const uint32_t base = (smem_u32(smraw) + 1023u) & ~1023u;
    const uint32_t XT  = base;
    const uint32_t CT  = base + 32768;
    const uint32_t WB0 = base + 65536;
    const uint32_t WB1 = base + 81920;
    const uint32_t SC  = base + 98304;
    const uint32_t SH  = base + 163840;

    const int tid = threadIdx.x, wid = tid >> 5, lane = tid & 31;
    const int m0 = blockIdx.x * 64;
    const int warp_m = (wid & 3) * 16;   // 4 warps down M (64)
    const int warp_n = (wid >> 2) * 64;  // 4 warps across N (256)

    // ---- Stage x & ctx tiles: 64 rows x 256 fp32 -> fp16 chunk-major ----
    {
        const float* xp = x   + (size_t)m0 * CDIM;
        const float* cp = ctx + (size_t)m0 * CDIM;
        #pragma unroll
        for (int i = 0; i < 4; i++) {
            const int unit = i * 512 + tid;       // 2048 units of 8 floats
            const int row = unit >> 5, u = unit & 31;
            const int kc = u >> 2, c = u & 3;
            const uint32_t so = (uint32_t)(kc * 4096) + tile_off(row, c);
            const float4* p = (const float4*)(xp + row * CDIM + u * 8);
            float4 f0 = p[0], f1 = p[1];
            uint4 v;
            v.x = packh2(f0.x, f0.y); v.y = packh2(f0.z, f0.w);
            v.z = packh2(f1.x, f1.y); v.w = packh2(f1.z, f1.w);
            asm volatile("st.shared.v4.b32 [%0], {%1,%2,%3,%4};" ::
                "r"(XT + so), "r"(v.x), "r"(v.y), "r"(v.z), "r"(v.w) : "memory");
            p = (const float4*)(cp + row * CDIM + u * 8);
            f0 = p[0]; f1 = p[1];
            v.x = packh2(f0.x, f0.y); v.y = packh2(f0.z, f0.w);
            v.z = packh2(f1.x, f1.y); v.w = packh2(f1.z, f1.w);
            asm volatile("st.shared.v4.b32 [%0], {%1,%2,%3,%4};" ::
                "r"(CT + so), "r"(v.x), "r"(v.y), "r"(v.z), "r"(v.w) : "memory");
        }
    }
    __syncthreads();

    // cp.async weight stage: 16KB block, 512 threads x 32B.
    auto ldw_async = [&](int mat, int kt, uint32_t buf) {
        const uint8_t* src = (const uint8_t*)g_wh
                           + ((size_t)(mat * 8 + kt) << 14) + tid * 32;
        const uint32_t d0 = buf + tid * 32;
        CP_ASYNC16(d0,      src);
        CP_ASYNC16(d0 + 16, src + 16);
        CP_COMMIT();
    };

    float d[8][4];
    auto do_gemm = [&](int mat, uint32_t at) {
        #pragma unroll
        for (int nt = 0; nt < 8; nt++)
            #pragma unroll
            for (int i = 0; i < 4; i++) d[nt][i] = 0.f;
        ldw_async(mat, 0, WB0);
        #pragma unroll 1
        for (int kt = 0; kt < 8; kt++) {
            CP_WAIT0();
            __syncthreads();
            if (kt < 7) ldw_async(mat, kt + 1, (kt & 1) ? WB0 : WB1);
            const uint32_t wb = (kt & 1) ? WB1 : WB0;
            const uint32_t ac = at + kt * 4096;
            #pragma unroll
            for (int s = 0; s < 2; s++) {
                uint32_t a[4];
                const int R = warp_m + (lane & 15);
                const int c = s * 2 + (lane >> 4);
                LDSM_X4(a[0], a[1], a[2], a[3], ac + tile_off(R, c));
                #pragma unroll
                for (int np = 0; np < 4; np++) {
                    const int g = lane >> 3, lr = lane & 7;
                    const int Rn = warp_n + np * 16 + ((g >> 1) << 3) + lr;
                    const int cb = s * 2 + (g & 1);
                    uint32_t b[4];
                    LDSM_X4(b[0], b[1], b[2], b[3], wb + tile_off(Rn, cb));
                    MMA16816(d[np * 2 + 0], a, b[0], b[1]);
                    MMA16816(d[np * 2 + 1], a, b[2], b[3]);
                }
            }
        }
    };

    // shifted fp32 [64][256] smem accessors (write/read same-thread)
    auto smoff = [&](int row, int col) -> uint32_t {
        const int colp = (col + row * 8) & 255;
        return (uint32_t)(row * 1024 + colp * 4);
    };

    // ---- scale, shift (from ctx tile) -> smem (fp32, bit-identical) ----
    const uint32_t Sm[2] = {SC, SH};
    #pragma unroll 1
    for (int mphase = 0; mphase < 2; mphase++) {
        do_gemm(mphase, CT);                 // mat 0=Wscale, 1=Wshift
        #pragma unroll
        for (int half = 0; half < 2; half++) {
            const int row = warp_m + (lane >> 2) + half * 8;
            #pragma unroll
            for (int nt = 0; nt < 8; nt++) {
                const int col = warp_n + nt * 8 + (lane & 3) * 2;
                asm volatile("st.shared.v2.b32 [%0], {%1,%2};" ::
                    "r"(Sm[mphase] + smoff(row, col)),
                    "r"(__float_as_uint(d[nt][half * 2 + 0])),
                    "r"(__float_as_uint(d[nt][half * 2 + 1])) : "memory");
            }
        }
        __syncthreads();
    }

    // ---- q, k, v (from x tile) with fused FiLM; fp16 stores ----
    __half* Outs[3] = {outq, outk, outv};
    #pragma unroll 1
    for (int mphase = 0; mphase < 3; mphase++) {
        do_gemm(2 + mphase, XT);             // mats 2=Wq, 3=Wk, 4=Wv
        __half* outp = Outs[mphase];
        #pragma unroll
        for (int half = 0; half < 2; half++) {
            const int row = warp_m + (lane >> 2) + half * 8;
            const size_t rbase = (size_t)(m0 + row) * CDIM;
            #pragma unroll
            for (int nt = 0; nt < 8; nt++) {
                const int col = warp_n + nt * 8 + (lane & 3) * 2;
                uint32_t sx, sy, tx, ty;
                asm volatile("ld.shared.v2.b32 {%0,%1}, [%2];"
                    : "=r"(sx), "=r"(sy) : "r"(SC + smoff(row, col)));
                asm volatile("ld.shared.v2.b32 {%0,%1}, [%2];"
                    : "=r"(tx), "=r"(ty) : "r"(SH + smoff(row, col)));
                const float vx = fmaf(__uint_as_float(sx), d[nt][half * 2 + 0],
                                      __uint_as_float(tx));
                const float vy = fmaf(__uint_as_float(sy), d[nt][half * 2 + 1],
                                      __uint_as_float(ty));
                *(uint32_t*)(outp + rbase + col) = packh2(vx, vy);
            }
        }
        __syncthreads();
    }
}

// ---------------------------------------------------------------------------
// Out-projection GEMM (exact R11 form): out = A @ Wout^T, K=256.
// ---------------------------------------------------------------------------
__global__ void __launch_bounds__(256)
gemm_h16(const __half* __restrict__ A, float* __restrict__ out)
{
    __shared__ alignas(128) uint8_t sA[2][8192];
    __shared__ alignas(128) uint8_t sB[2][8192];

    const int tid  = threadIdx.x;
    const int wid  = tid >> 5;
    const int lane = tid & 31;
    const int m0 = blockIdx.y * 128;
    const int n0 = blockIdx.x * 128;

    const int warp_m = (wid & 3) * 32;
    const int warp_n = (wid >> 2) * 64;

    const uint32_t sa0 = smem_u32(&sA[0][0]);
    const uint32_t sa1 = smem_u32(&sA[1][0]);
    const uint32_t sb0 = smem_u32(&sB[0][0]);
    const uint32_t sb1 = smem_u32(&sB[1][0]);

    float d[2][8][4];
    #pragma unroll
    for (int mt = 0; mt < 2; mt++)
        #pragma unroll
        for (int nt = 0; nt < 8; nt++)
            #pragma unroll
            for (int i = 0; i < 4; i++) d[mt][nt][i] = 0.f;

    auto ldab_async = [&](int kt, uint32_t abuf, uint32_t bbuf) {
        #pragma unroll
        for (int u = 0; u < 2; u++) {
            const int idx = tid + u * 256;
            const int row = idx >> 2, c = idx & 3;
            const __half* src = A + (size_t)(m0 + row) * CDIM + kt * 32 + c * 8;
            CP_ASYNC16(abuf + tile_off(row, c), src);
        }
        const uint8_t* bsrc = (const uint8_t*)g_wh + ((size_t)(40 + kt) << 14)
                            + n0 * 64 + tid * 32;
        const uint32_t d0 = bbuf + tid * 32;
        CP_ASYNC16(d0,      bsrc);
        CP_ASYNC16(d0 + 16, bsrc + 16);
        CP_COMMIT();
    };

    ldab_async(0, sa0, sb0);

    #pragma unroll 1
    for (int kt = 0; kt < 8; kt++) {
        CP_WAIT0();
        __syncthreads();
        if (kt < 7) ldab_async(kt + 1, (kt & 1) ? sa0 : sa1, (kt & 1) ? sb0 : sb1);
        const uint32_t abuf = (kt & 1) ? sa1 : sa0;
        const uint32_t bbuf = (kt & 1) ? sb1 : sb0;

        #pragma unroll
        for (int ks = 0; ks < 2; ks++) {
            uint32_t a[2][4];
            #pragma unroll
            for (int mt = 0; mt < 2; mt++) {
                const int R = warp_m + mt * 16 + (lane & 15);
                const int c = ks * 2 + (lane >> 4);
                LDSM_X4(a[mt][0], a[mt][1], a[mt][2], a[mt][3],
                        abuf + tile_off(R, c));
            }
            #pragma unroll
            for (int np = 0; np < 4; np++) {
                const int g = lane >> 3, lr = lane & 7;
                const int Rn = warp_n + np * 16 + ((g >> 1) << 3) + lr;
                const int c = ks * 2 + (g & 1);
                uint32_t b[4];
                LDSM_X4(b[0], b[1], b[2], b[3], bbuf + tile_off(Rn, c));
                #pragma unroll
                for (int mt = 0; mt < 2; mt++) {
                    MMA16816(d[mt][np * 2 + 0], a[mt], b[0], b[1]);
                    MMA16816(d[mt][np * 2 + 1], a[mt], b[2], b[3]);
                }
            }
        }
    }

    #pragma unroll
    for (int mt = 0; mt < 2; mt++) {
        #pragma unroll
        for (int half = 0; half < 2; half++) {
            const int row = m0 + warp_m + mt * 16 + (lane >> 2) + half * 8;
            const size_t rbase = (size_t)row * CDIM;
            #pragma unroll
            for (int nt = 0; nt < 8; nt++) {
                const int col = n0 + warp_n + nt * 8 + (lane & 3) * 2;
                float2 v;
                v.x = d[mt][nt][half * 2 + 0];
                v.y = d[mt][nt][half * 2 + 1];
                *(float2*)(out + rbase + col) = v;
            }
        }
    }
}

// ---------------------------------------------------------------------------
// Tensor-core attention v3: 256 threads (8 warps, 16 rows/warp).
// Same math/order as R11 (bit-identical); just more warps, fewer regs each.
// ---------------------------------------------------------------------------
#define AT_SMEM (57344 + 1024)

__global__ void __launch_bounds__(256)
attn_mma(const __half* __restrict__ Qg, const __half* __restrict__ Kg,
         const __half* __restrict__ Vg, __half* __restrict__ O)
{
    extern __shared__ uint8_t smraw[];
    const uint32_t base = (smem_u32(smraw) + 1023u) & ~1023u;
    const uint32_t SQ = base;
    const uint32_t SK = base + 8192;
    const uint32_t SVT = base + 16384;   // 4 chunks x 2KB, [32 e][32 j]
    const uint32_t SP = base + 24576;    // 4 chunks x 8KB, [128 m][32 j]

    const int tid = threadIdx.x, wid = tid >> 5, lane = tid & 31;
    const int bh = blockIdx.x;
    const size_t r0 = (size_t)(bh >> 3) * 128;
    const int c0 = (bh & 7) * 32;
    const int warp_m = wid * 16;          // 8 warps x 16 rows

    // ---- Stage Q, K (fp16 copies) and V transposed; 256 threads ----
    {
        const int part = tid & 3;
        #pragma unroll
        for (int pass = 0; pass < 2; pass++) {
            const int row = (tid >> 2) + pass * 64;
            const uint4 qv = *(const uint4*)(Qg + (r0 + row) * CDIM + c0 + part * 8);
            asm volatile("st.shared.v4.b32 [%0], {%1,%2,%3,%4};" ::
                "r"(SQ + tile_off(row, part)), "r"(qv.x), "r"(qv.y), "r"(qv.z), "r"(qv.w) : "memory");
            const uint4 kv = *(const uint4*)(Kg + (r0 + row) * CDIM + c0 + part * 8);
            asm volatile("st.shared.v4.b32 [%0], {%1,%2,%3,%4};" ::
                "r"(SK + tile_off(row, part)), "r"(kv.x), "r"(kv.y), "r"(kv.z), "r"(kv.w) : "memory");
        }
        #pragma unroll
        for (int pass = 0; pass < 2; pass++) {
            const int j = (tid >> 2) + pass * 64;
            const int e0 = part * 8;
            const uint4 vv = *(const uint4*)(Vg + (r0 + j) * CDIM + c0 + e0);
            const uint16_t* hw = (const uint16_t*)&vv;
            const uint32_t cb = SVT + (j >> 5) * 2048;
            const int jc = j & 31;
            #pragma unroll
            for (int i = 0; i < 8; i++) {
                asm volatile("st.shared.b16 [%0], %1;" ::
                    "r"(cb + tile_off(e0 + i, jc >> 3) + (jc & 7) * 2), "h"(hw[i]) : "memory");
            }
        }
    }
    __syncthreads();

    // ---- QK^T: S[warp_m..+16][0..128) in registers ----
    float d[16][4];
    #pragma unroll
    for (int nt = 0; nt < 16; nt++)
        #pragma unroll
        for (int i = 0; i < 4; i++) d[nt][i] = 0.f;

    #pragma unroll
    for (int s = 0; s < 2; s++) {
        uint32_t a[4];
        const int R = warp_m + (lane & 15);
        const int c = s * 2 + (lane >> 4);
        LDSM_X4(a[0], a[1], a[2], a[3], SQ + tile_off(R, c));
        #pragma unroll
        for (int np = 0; np < 8; np++) {
            const int g = lane >> 3, lr = lane & 7;
            const int Rn = np * 16 + ((g >> 1) << 3) + lr;
            const int cb = s * 2 + (g & 1);
            uint32_t b[4];
            LDSM_X4(b[0], b[1], b[2], b[3], SK + tile_off(Rn, cb));
            MMA16816(d[np * 2 + 0], a, b[0], b[1]);
            MMA16816(d[np * 2 + 1], a, b[2], b[3]);
        }
    }

    // ---- Softmax per row; P -> smem fp16 ----
    const float sc = 0.17677669529663687f;
    float inv[2];
    #pragma unroll
    for (int half = 0; half < 2; half++) {
        float mx = -1e30f;
        #pragma unroll
        for (int nt = 0; nt < 16; nt++)
            mx = fmaxf(mx, fmaxf(d[nt][half * 2], d[nt][half * 2 + 1]));
        mx = fmaxf(mx, __shfl_xor_sync(0xffffffffu, mx, 1));
        mx = fmaxf(mx, __shfl_xor_sync(0xffffffffu, mx, 2));
        const float mxs = mx * sc;
        float sum = 0.f;
        const int row = warp_m + (lane >> 2) + half * 8;
        #pragma unroll
        for (int nt = 0; nt < 16; nt++) {
            const float p0 = __expf(fmaf(d[nt][half * 2 + 0], sc, -mxs));
            const float p1 = __expf(fmaf(d[nt][half * 2 + 1], sc, -mxs));
            sum += p0 + p1;
            const int jc = (nt & 3) * 8 + (lane & 3) * 2;
            asm volatile("st.shared.b32 [%0], %1;" ::
                "r"(SP + (nt >> 2) * 8192 + tile_off(row, jc >> 3) + (jc & 7) * 2),
                "r"(packh2(p0, p1)) : "memory");
        }
        sum += __shfl_xor_sync(0xffffffffu, sum, 1);
        sum += __shfl_xor_sync(0xffffffffu, sum, 2);
        inv[half] = 1.f / sum;
    }
    __syncwarp();   // this warp's P rows are consumed only by this warp

    // ---- PV: O[warp rows][32] ----
    float o[4][4];
    #pragma unroll
    for (int nt = 0; nt < 4; nt++)
        #pragma unroll
        for (int i = 0; i < 4; i++) o[nt][i] = 0.f;

    #pragma unroll
    for (int ck = 0; ck < 4; ck++) {
        const uint32_t pb = SP + ck * 8192;
        const uint32_t vb = SVT + ck * 2048;
        #pragma unroll
        for (int s = 0; s < 2; s++) {
            uint32_t a[4];
            const int R = warp_m + (lane & 15);
            const int c = s * 2 + (lane >> 4);
            LDSM_X4(a[0], a[1], a[2], a[3], pb + tile_off(R, c));
            #pragma unroll
            for (int np = 0; np < 2; np++) {
                const int g = lane >> 3, lr = lane & 7;
                const int Rn = np * 16 + ((g >> 1) << 3) + lr;
                const int cb = s * 2 + (g & 1);
                uint32_t b[4];
                LDSM_X4(b[0], b[1], b[2], b[3], vb + tile_off(Rn, cb));
                MMA16816(o[np * 2 + 0], a, b[0], b[1]);
                MMA16816(o[np * 2 + 1], a, b[2], b[3]);
            }
        }
    }

    // ---- Epilogue: normalize, fp16 store ----
    #pragma unroll
    for (int half = 0; half < 2; half++) {
        const int row = warp_m + (lane >> 2) + half * 8;
        const float iv = inv[half];
        const size_t rbase = (r0 + row) * CDIM + c0;
        #pragma unroll
        for (int nt = 0; nt < 4; nt++) {
            const int col = nt * 8 + (lane & 3) * 2;
            *(uint32_t*)(O + rbase + col) =
                packh2(o[nt][half * 2 + 0] * iv,
                       o[nt][half * 2 + 1] * iv);
        }
    }
}

// ---------------------------------------------------------------------------
// Launch
// ---------------------------------------------------------------------------
extern "C" void kernel_launch(void* const* d_in, const int* in_sizes, int n_in,
                              void* d_out, int out_size)
{
    const float* x      = (const float*)d_in[0];
    const float* ctx    = (const float*)d_in[1];
    const float* Wq     = (const float*)d_in[2];
    const float* Wkv    = (const float*)d_in[3];
    const float* Wout   = (const float*)d_in[4];
    const float* Wscale = (const float*)d_in[5];
    const float* Wshift = (const float*)d_in[6];
    float* out = (float*)d_out;

    __half *gq, *gk, *gv, *ga;
    cudaGetSymbolAddress((void**)&gq, g_q);
    cudaGetSymbolAddress((void**)&gk, g_k);
    cudaGetSymbolAddress((void**)&gv, g_v);
    cudaGetSymbolAddress((void**)&ga, g_attn);

    cudaFuncSetAttribute(fused_proj,
                         cudaFuncAttributeMaxDynamicSharedMemorySize, FP_SMEM);
    cudaFuncSetAttribute(attn_mma,
                         cudaFuncAttributeMaxDynamicSharedMemorySize, AT_SMEM);

    wcvt<<<48, 256>>>(Wq, Wkv, Wscale, Wshift, Wout);
    fused_proj<<<MROWS / 64, 512, FP_SMEM>>>(x, ctx, gq, gk, gv);
    attn_mma<<<8192, 256, AT_SMEM>>>(gq, gk, gv, ga);
    gemm_h16<<<dim3(2, 1024), 256>>>(ga, out);
}